// round 1
// baseline (speedup 1.0000x reference)
#include <cuda_runtime.h>
#include <cuda_bf16.h>

#define N_NODES  50000
#define N_EDGES  800000
#define N_GRAPHS 64
#define IN_DIM   384
#define HID      128
#define MLP_HID  64

// ---------------- scratch (alloc-free: __device__ globals) ----------------
__device__ float g_dis[N_NODES];            // deg accumulation, then rsqrt(deg+1)
__device__ float g_h0[N_NODES * HID];
__device__ float g_h1[N_NODES * HID];
__device__ float g_agg[N_NODES * HID];
__device__ float g_pool[N_GRAPHS * HID];
__device__ float g_cnt[N_GRAPHS];

__device__ __forceinline__ float* hbuf(int b) { return b ? g_h1 : g_h0; }

// ---------------- zero scratch that needs zeroing each call ----------------
__global__ void k_zero() {
    int i = blockIdx.x * blockDim.x + threadIdx.x;
    if (i < N_NODES)          g_dis[i] = 0.f;
    if (i < N_GRAPHS * HID)   g_pool[i] = 0.f;
    if (i < N_GRAPHS)         g_cnt[i] = 0.f;
}

// ---------------- degree + normalization ----------------
__global__ void k_degree(const int* __restrict__ dst) {
    int e = blockIdx.x * blockDim.x + threadIdx.x;
    if (e < N_EDGES) atomicAdd(&g_dis[dst[e]], 1.f);
}

__global__ void k_rsqrt() {
    int i = blockIdx.x * blockDim.x + threadIdx.x;
    if (i < N_NODES) g_dis[i] = rsqrtf(g_dis[i] + 1.f);
}

// ---------------- GEMM: C[M,128] = A[M,K] @ W[K,128]; epilogue writes H and AGG=C*dis^2
template <int K>
__global__ void __launch_bounds__(256)
k_gemm(const float* __restrict__ Aext, int a_sel,
       const float* __restrict__ W, int h_sel) {
    __shared__ float As[64][16];
    __shared__ float Bs[16][128];

    const float* A = (a_sel < 0) ? Aext : hbuf(a_sel);
    float* H = hbuf(h_sel);

    int m0  = blockIdx.x * 64;
    int tid = threadIdx.x;
    int cx  = tid & 31;        // 0..31  -> col0 = cx*4
    int ry  = tid >> 5;        // 0..7   -> row0 = ry*8
    int col0 = cx * 4;
    int row0 = ry * 8;

    float acc[8][4];
#pragma unroll
    for (int i = 0; i < 8; i++)
#pragma unroll
        for (int j = 0; j < 4; j++) acc[i][j] = 0.f;

    for (int k0 = 0; k0 < K; k0 += 16) {
        // load A tile: 64x16 = 1024 floats, float4 per thread
        {
            int r = tid >> 2;
            int c = (tid & 3) * 4;
            int row = m0 + r;
            float4 v = make_float4(0.f, 0.f, 0.f, 0.f);
            if (row < N_NODES) v = *(const float4*)&A[(long)row * K + k0 + c];
            *(float4*)&As[r][c] = v;
        }
        // load B tile: 16x128 = 2048 floats, 2x float4 per thread
        {
            int r = tid >> 4;
            int c = (tid & 15) * 8;
            const float* wp = &W[(k0 + r) * 128 + c];
            *(float4*)&Bs[r][c]     = *(const float4*)&wp[0];
            *(float4*)&Bs[r][c + 4] = *(const float4*)&wp[4];
        }
        __syncthreads();
#pragma unroll
        for (int kk = 0; kk < 16; kk++) {
            float4 bv = *(const float4*)&Bs[kk][col0];
#pragma unroll
            for (int i = 0; i < 8; i++) {
                float a = As[row0 + i][kk];
                acc[i][0] = fmaf(a, bv.x, acc[i][0]);
                acc[i][1] = fmaf(a, bv.y, acc[i][1]);
                acc[i][2] = fmaf(a, bv.z, acc[i][2]);
                acc[i][3] = fmaf(a, bv.w, acc[i][3]);
            }
        }
        __syncthreads();
    }

#pragma unroll
    for (int i = 0; i < 8; i++) {
        int row = m0 + row0 + i;
        if (row < N_NODES) {
            float ds = g_dis[row];
            ds = ds * ds;
            float4 v = make_float4(acc[i][0], acc[i][1], acc[i][2], acc[i][3]);
            *(float4*)&H[row * 128 + col0] = v;
            float4 w = make_float4(v.x * ds, v.y * ds, v.z * ds, v.w * ds);
            *(float4*)&g_agg[row * 128 + col0] = w;
        }
    }
}

// ---------------- edge scatter: warp per edge, vector RED into agg ----------------
__global__ void __launch_bounds__(256)
k_scatter(const int* __restrict__ src, const int* __restrict__ dst, int h_sel) {
    int gthr = blockIdx.x * blockDim.x + threadIdx.x;
    int e    = gthr >> 5;
    int lane = gthr & 31;
    if (e >= N_EDGES) return;
    const float* H = hbuf(h_sel);

    int s = src[e];
    int d = dst[e];
    float en = g_dis[s] * g_dis[d];

    float4 v = *(const float4*)&H[s * 128 + lane * 4];
    float* p = &g_agg[d * 128 + lane * 4];
    asm volatile("red.global.add.v4.f32 [%0], {%1,%2,%3,%4};"
                 :: "l"(p), "f"(v.x * en), "f"(v.y * en), "f"(v.z * en), "f"(v.w * en)
                 : "memory");
}

// ---------------- finalize: Hout = relu(agg + bias) ----------------
__global__ void __launch_bounds__(256)
k_finalize(const float* __restrict__ bias, int out_sel) {
    int i = blockIdx.x * blockDim.x + threadIdx.x;   // float4 index
    if (i >= N_NODES * 32) return;
    float* Hout = hbuf(out_sel);
    float4 v = *(const float4*)&g_agg[i * 4];
    float4 b = *(const float4*)&bias[(i & 31) * 4];
    v.x = fmaxf(v.x + b.x, 0.f);
    v.y = fmaxf(v.y + b.y, 0.f);
    v.z = fmaxf(v.z + b.z, 0.f);
    v.w = fmaxf(v.w + b.w, 0.f);
    *(float4*)&Hout[i * 4] = v;
}

// ---------------- pooling ----------------
__global__ void k_count(const int* __restrict__ batch) {
    int i = blockIdx.x * blockDim.x + threadIdx.x;
    if (i < N_NODES) atomicAdd(&g_cnt[batch[i]], 1.f);
}

__global__ void __launch_bounds__(256)
k_pool(const int* __restrict__ batch, int h_sel) {
    int i = blockIdx.x * blockDim.x + threadIdx.x;   // float4 index
    if (i >= N_NODES * 32) return;
    const float* H = hbuf(h_sel);
    int node = i >> 5;
    int f4   = i & 31;
    int g    = batch[node];
    float4 v = *(const float4*)&H[i * 4];
    float* p = &g_pool[g * 128 + f4 * 4];
    asm volatile("red.global.add.v4.f32 [%0], {%1,%2,%3,%4};"
                 :: "l"(p), "f"(v.x), "f"(v.y), "f"(v.z), "f"(v.w)
                 : "memory");
}

// ---------------- MLP head: out[g] = relu(pooled @ Wm1 + bm1) @ Wm2 + bm2 ----------------
__global__ void k_mlp(const float* __restrict__ Wm1, const float* __restrict__ bm1,
                      const float* __restrict__ Wm2, const float* __restrict__ bm2,
                      float* __restrict__ out) {
    int g = blockIdx.x;
    int j = threadIdx.x;   // 64 threads
    __shared__ float p[128];
    __shared__ float red[64];

    float cnt = fmaxf(g_cnt[g], 1.f);
    p[j]      = g_pool[g * 128 + j] / cnt;
    p[j + 64] = g_pool[g * 128 + 64 + j] / cnt;
    __syncthreads();

    float z = bm1[j];
#pragma unroll 8
    for (int k = 0; k < 128; k++) z = fmaf(p[k], Wm1[k * 64 + j], z);
    z = fmaxf(z, 0.f);
    z *= Wm2[j];

    red[j] = z;
    __syncthreads();
#pragma unroll
    for (int s = 32; s > 0; s >>= 1) {
        if (j < s) red[j] += red[j + s];
        __syncthreads();
    }
    if (j == 0) out[g] = red[0] + bm2[0];
}

// ---------------- launch ----------------
extern "C" void kernel_launch(void* const* d_in, const int* in_sizes, int n_in,
                              void* d_out, int out_size) {
    const float* x    = (const float*)d_in[0];
    const int*   ei   = (const int*)  d_in[1];
    const int*   batch= (const int*)  d_in[2];
    const float* W1   = (const float*)d_in[3];
    const float* b1   = (const float*)d_in[4];
    const float* W2   = (const float*)d_in[5];
    const float* b2   = (const float*)d_in[6];
    const float* W3   = (const float*)d_in[7];
    const float* b3   = (const float*)d_in[8];
    const float* Wm1  = (const float*)d_in[9];
    const float* bm1  = (const float*)d_in[10];
    const float* Wm2  = (const float*)d_in[11];
    const float* bm2  = (const float*)d_in[12];
    const int* src = ei;
    const int* dst = ei + N_EDGES;
    float* out = (float*)d_out;

    const int ZB   = (N_NODES + 255) / 256;            // 196
    const int EB   = (N_EDGES + 255) / 256;            // 3125
    const int GB   = (N_NODES + 63) / 64;              // 782
    const int SB   = (N_EDGES * 32) / 256;             // 100000
    const int FB   = (N_NODES * 32 + 255) / 256;       // 6250

    k_zero  <<<ZB, 256>>>();
    k_degree<<<EB, 256>>>(dst);
    k_rsqrt <<<ZB, 256>>>();

    // layer 1: A = x (ext), out h_sel=0
    k_gemm<IN_DIM><<<GB, 256>>>(x, -1, W1, 0);
    k_scatter<<<SB, 256>>>(src, dst, 0);
    k_finalize<<<FB, 256>>>(b1, 1);

    // layer 2: A = h1, out h0
    k_gemm<HID><<<GB, 256>>>(nullptr, 1, W2, 0);
    k_scatter<<<SB, 256>>>(src, dst, 0);
    k_finalize<<<FB, 256>>>(b2, 1);

    // layer 3: A = h1, out h0
    k_gemm<HID><<<GB, 256>>>(nullptr, 1, W3, 0);
    k_scatter<<<SB, 256>>>(src, dst, 0);
    k_finalize<<<FB, 256>>>(b3, 1);

    // pooling + MLP
    k_count<<<ZB, 256>>>(batch);
    k_pool <<<FB, 256>>>(batch, 1);
    k_mlp  <<<N_GRAPHS, 64>>>(Wm1, bm1, Wm2, bm2, out);
}